// round 5
// baseline (speedup 1.0000x reference)
#include <cuda_runtime.h>
#include <cuda_bf16.h>

#define HDIM 16
#define UDIM 7
#define HID  64
#define XDIM 23
#define CHUNK 512
#define NTHREADS 96

typedef unsigned long long u64;

__device__ __forceinline__ unsigned smem_u32(const void* p) {
    return (unsigned)__cvta_generic_to_shared(p);
}
__device__ __forceinline__ void cp16(unsigned dst, const void* src) {
    asm volatile("cp.async.cg.shared.global [%0], [%1], 16;" :: "r"(dst), "l"(src));
}
__device__ __forceinline__ void cp4(unsigned dst, const void* src) {
    asm volatile("cp.async.ca.shared.global [%0], [%1], 4;" :: "r"(dst), "l"(src));
}
__device__ __forceinline__ void cp_commit() {
    asm volatile("cp.async.commit_group;" ::: "memory");
}
__device__ __forceinline__ void cp_wait1() {
    asm volatile("cp.async.wait_group 1;" ::: "memory");
}

// packed f32x2 helpers (B300: fma.rn.f32x2 only reachable via PTX)
__device__ __forceinline__ u64 pack2(float lo, float hi) {
    u64 r; asm("mov.b64 %0, {%1, %2};" : "=l"(r) : "f"(lo), "f"(hi)); return r;
}
__device__ __forceinline__ float2 unpack2(u64 v) {
    float2 f; asm("mov.b64 {%0, %1}, %2;" : "=f"(f.x), "=f"(f.y) : "l"(v)); return f;
}
__device__ __forceinline__ u64 fma2(u64 a, u64 b, u64 c) {
    u64 r; asm("fma.rn.f32x2 %0, %1, %2, %3;" : "=l"(r) : "l"(a), "l"(b), "l"(c)); return r;
}
__device__ __forceinline__ u64 add2(u64 a, u64 b) {
    u64 r; asm("add.rn.f32x2 %0, %1, %2;" : "=l"(r) : "l"(a), "l"(b)); return r;
}

// accurate-enough tanh: (e^{2x}-1)/(e^{2x}+1), clamped
__device__ __forceinline__ float ftanh(float x) {
    x = fminf(fmaxf(x, -15.0f), 15.0f);
    float e = __expf(2.0f * x);
    return __fdividef(e - 1.0f, e + 1.0f);
}

// 64-wide dot: 32 packed weights (registers or smem) x 64 floats in 16B-aligned smem
__device__ __forceinline__ float dot64(const u64* __restrict__ wp,
                                       const float* __restrict__ zs, u64 init) {
    const ulonglong2* zp = (const ulonglong2*)zs;
    u64 a0 = init, a1 = 0ull, a2 = 0ull, a3 = 0ull;
    #pragma unroll
    for (int j = 0; j < 16; j += 2) {
        ulonglong2 q0 = zp[j];
        ulonglong2 q1 = zp[j + 1];
        a0 = fma2(wp[2 * j + 0], q0.x, a0);
        a1 = fma2(wp[2 * j + 1], q0.y, a1);
        a2 = fma2(wp[2 * j + 2], q1.x, a2);
        a3 = fma2(wp[2 * j + 3], q1.y, a3);
    }
    a0 = add2(a0, a1);
    a2 = add2(a2, a3);
    a0 = add2(a0, a2);
    float2 f = unpack2(a0);
    return f.x + f.y;
}

__global__ void __launch_bounds__(NTHREADS, 1) node_scan_kernel(
    const float* __restrict__ U,
    const float* __restrict__ W1, const float* __restrict__ b1,
    const float* __restrict__ W2, const float* __restrict__ b2,
    const float* __restrict__ W3, const float* __restrict__ b3,
    const float* __restrict__ wd, const float* __restrict__ bd,
    const float* __restrict__ wt, const float* __restrict__ bt,
    const float* __restrict__ wc, const float* __restrict__ bc,
    const float* __restrict__ h0,
    float* __restrict__ out, int T)
{
    __shared__ __align__(16) float ubuf[2][CHUNK * UDIM];
    __shared__ __align__(16) float z1s[HID];
    __shared__ __align__(16) float z2s[HID];
    __shared__ __align__(16) float rvs[3][HID];   // dt * (W3^T w_sel), per readout
    __shared__ __align__(16) double sumz2[HID];

    const int tid = threadIdx.x;
    const float dt = 5.0f / 60.0f;
    const int n_chunks = (T + CHUNK - 1) / CHUNK;

    auto copy_chunk = [&](int cc) {
        if (cc >= n_chunks) return;
        const int t0 = cc * CHUNK;
        const int nf = min(CHUNK, T - t0) * UDIM;
        const float* src = U + t0 * UDIM;
        float* dst = ubuf[cc & 1];
        const int nv = nf >> 2;
        for (int i = tid; i < nv; i += NTHREADS) cp16(smem_u32(dst + 4 * i), src + 4 * i);
        for (int i = (nv << 2) + tid; i < nf; i += NTHREADS) cp4(smem_u32(dst + i), src + i);
    };
    copy_chunk(0); cp_commit();
    copy_chunk(1); cp_commit();

    // ---------------- prologue (overlaps with cp.async in flight) ----------------
    u64 w2p[32], Mp[32];
    float w1u[UDIM];
    float s = 0.0f, du = 0.0f;
    double accz2 = 0.0;
    u64 b2p = 0ull, cdtp = 0ull, rofsp = 0ull;
    float r_sc = 0.0f;
    float* outp = nullptr;

    if (tid < HID) {
        float w1h[HDIM];
        #pragma unroll
        for (int i = 0; i < HDIM; i++) w1h[i] = W1[tid * XDIM + i];
        #pragma unroll
        for (int i = 0; i < UDIM; i++) w1u[i] = W1[tid * XDIM + HDIM + i];
        // s_0 = W1h @ h0 + b1   (state kept instead of h)
        s = b1[tid];
        #pragma unroll
        for (int i = 0; i < HDIM; i++) s = fmaf(w1h[i], h0[i], s);
        #pragma unroll
        for (int j = 0; j < 32; j++)
            w2p[j] = pack2(W2[tid * HID + 2 * j], W2[tid * HID + 2 * j + 1]);
        b2p = pack2(b2[tid], 0.0f);
        // M = dt * (W1h @ W3): fused state-update matrix
        #pragma unroll 4
        for (int j = 0; j < 32; j++) {
            float m0 = 0.0f, m1 = 0.0f;
            #pragma unroll
            for (int i = 0; i < HDIM; i++) {
                m0 = fmaf(w1h[i], W3[i * HID + 2 * j], m0);
                m1 = fmaf(w1h[i], W3[i * HID + 2 * j + 1], m1);
            }
            Mp[j] = pack2(dt * m0, dt * m1);
        }
        float cdt = 0.0f;
        #pragma unroll
        for (int i = 0; i < HDIM; i++) cdt = fmaf(w1h[i], b3[i], cdt);
        cdtp = pack2(dt * cdt, 0.0f);
    } else if (tid < HID + 3) {
        const int idx = tid - HID;
        const float* wsel = (idx == 0) ? wd : (idx == 1) ? wt : wc;
        const float bsel = (idx == 0) ? bd[0] : (idx == 1) ? bt[0] : bc[0];
        float ws[HDIM];
        #pragma unroll
        for (int i = 0; i < HDIM; i++) ws[i] = wsel[i];
        r_sc = bsel;
        #pragma unroll
        for (int i = 0; i < HDIM; i++) r_sc = fmaf(ws[i], h0[i], r_sc);
        for (int j = 0; j < HID; j++) {
            float m = 0.0f;
            #pragma unroll
            for (int i = 0; i < HDIM; i++) m = fmaf(ws[i], W3[i * HID + j], m);
            rvs[idx][j] = dt * m;
        }
        float ro = 0.0f;
        #pragma unroll
        for (int i = 0; i < HDIM; i++) ro = fmaf(ws[i], b3[i], ro);
        rofsp = pack2(dt * ro, 0.0f);
        outp = out + idx * T;
    }

    // ---------------- main loop: 2 barriers per step ----------------
    for (int c = 0; c < n_chunks; c++) {
        cp_wait1();
        __syncthreads();                       // chunk data + prologue smem visible
        const int nst = min(CHUNK, T - c * CHUNK);
        const float* ub = ubuf[c & 1];
        const int tbase = c * CHUNK;

        if (tid < HID) {                       // du for first step of this chunk
            const float* up = ub;
            float d0 = w1u[0] * up[0], d1 = w1u[1] * up[1];
            d0 = fmaf(w1u[2], up[2], d0); d1 = fmaf(w1u[3], up[3], d1);
            d0 = fmaf(w1u[4], up[4], d0); d1 = fmaf(w1u[5], up[5], d1);
            d0 = fmaf(w1u[6], up[6], d0);
            du = d0 + d1;
        }

        for (int k = 0; k < nst; k++) {
            if (tid < HID) {
                // phase 1: z1 = tanh(s + du) — s already holds W1h@h + b1
                z1s[tid] = ftanh(s + du);
                // hoist next step's u-dot off the critical path
                if (k + 1 < nst) {
                    const float* up = ub + (k + 1) * UDIM;
                    float d0 = w1u[0] * up[0], d1 = w1u[1] * up[1];
                    d0 = fmaf(w1u[2], up[2], d0); d1 = fmaf(w1u[3], up[3], d1);
                    d0 = fmaf(w1u[4], up[4], d0); d1 = fmaf(w1u[5], up[5], d1);
                    d0 = fmaf(w1u[6], up[6], d0);
                    du = d0 + d1;
                }
            }
            __syncthreads();                   // bar1: z1s ready
            if (tid < HID) {
                // phase 2: z2 = tanh(W2 @ z1 + b2)
                float z2 = ftanh(dot64(w2p, z1s, b2p));
                z2s[tid] = z2;
                accz2 += (double)z2;           // exact hT reconstruction later
            }
            __syncthreads();                   // bar2: z2s ready
            if (tid < HID) {
                // phase 3: s += dt*(W1h@W3)@z2 + dt*W1h@b3
                s += dot64(Mp, z2s, cdtp);
            } else if (tid < HID + 3) {
                // readout at pre-update state, then linear scalar recurrence
                outp[tbase + k] = r_sc;
                r_sc += dot64((const u64*)rvs[tid - HID], z2s, rofsp);
            }
            // no third barrier: next z1s/z2s writes are fenced by bar1'/bar2'
        }
        copy_chunk(c + 2);
        cp_commit();
    }

    // ---------------- finalize hT = h0 + dt*(W3 @ sum(z2) + T*b3) in fp64 ----------------
    __syncthreads();
    if (tid < HID) sumz2[tid] = accz2;
    __syncthreads();
    if (tid < HDIM) {
        double acc = (double)T * (double)b3[tid];
        #pragma unroll 8
        for (int j = 0; j < HID; j++)
            acc += (double)W3[tid * HID + j] * sumz2[j];
        out[3 * T + tid] = (float)((double)h0[tid] + (double)dt * acc);
    }
}

extern "C" void kernel_launch(void* const* d_in, const int* in_sizes, int n_in,
                              void* d_out, int out_size)
{
    const int T = in_sizes[0] / UDIM;
    node_scan_kernel<<<1, NTHREADS>>>(
        (const float*)d_in[0],                          // U
        (const float*)d_in[1], (const float*)d_in[2],   // W1, b1
        (const float*)d_in[3], (const float*)d_in[4],   // W2, b2
        (const float*)d_in[5], (const float*)d_in[6],   // W3, b3
        (const float*)d_in[7], (const float*)d_in[8],   // wd, bd
        (const float*)d_in[9], (const float*)d_in[10],  // wt, bt
        (const float*)d_in[11], (const float*)d_in[12], // wc, bc
        (const float*)d_in[13],                         // h0
        (float*)d_out, T);
}